// round 1
// baseline (speedup 1.0000x reference)
#include <cuda_runtime.h>
#include <cuda_fp16.h>
#include <cstdint>

// ---------------- problem constants ----------------
#define NB     4096
#define SQ     81
#define DIM    256
#define NPOL   3849
#define NDROP  7
#define MROWS  (NB*SQ)          // 331776
#define SCALE  0.0625f          // 1/sqrt(256)

// ---------------- device scratch (no allocs allowed) ----------------
__device__ __align__(128) __half g_PE [(size_t)MROWS*256];   // mish(x@We+be), fp16
__device__ __align__(128) __half g_QK [(size_t)MROWS*512];   // [Q | K] fp16
__device__ __align__(128) __half g_WE [256*256];             // We^T  [n][k]
__device__ __align__(128) __half g_WQK[512*256];             // [Wq^T ; Wk^T] [n][k]
__device__ __align__(128) __half g_DQ [16*256];              // drop queries, zero padded
__device__ int g_MAP[NPOL];                                   // out slot p -> raw index

// ---------------- helpers ----------------
__device__ __forceinline__ uint32_t swz128(uint32_t o) { return o ^ ((o >> 3) & 0x70); }
__device__ __forceinline__ uint32_t swz512(uint32_t o) { return o ^ ((o >> 5) & 0x70); }

__device__ __forceinline__ uint32_t pack2(float a, float b) {
    __half2 h = __floats2half2_rn(a, b);
    return *reinterpret_cast<uint32_t*>(&h);
}

__device__ __forceinline__ void ldsm4(uint32_t& r0, uint32_t& r1, uint32_t& r2, uint32_t& r3, uint32_t addr) {
    asm volatile("ldmatrix.sync.aligned.m8n8.x4.shared.b16 {%0,%1,%2,%3}, [%4];\n"
                 : "=r"(r0), "=r"(r1), "=r"(r2), "=r"(r3) : "r"(addr));
}

__device__ __forceinline__ void mma16816(float* c, uint32_t a0, uint32_t a1, uint32_t a2, uint32_t a3,
                                         uint32_t b0, uint32_t b1) {
    asm volatile("mma.sync.aligned.m16n8k16.row.col.f32.f16.f16.f32 "
                 "{%0,%1,%2,%3},{%4,%5,%6,%7},{%8,%9},{%0,%1,%2,%3};\n"
                 : "+f"(c[0]), "+f"(c[1]), "+f"(c[2]), "+f"(c[3])
                 : "r"(a0), "r"(a1), "r"(a2), "r"(a3), "r"(b0), "r"(b1));
}

__device__ __forceinline__ float mishf(float v) {
    float sp = (v > 15.f) ? v : log1pf(expf(v));
    return v * tanhf(sp);
}

// ---------------- prep kernels ----------------
__global__ void prep_weights(const float* __restrict__ We, const float* __restrict__ Wq,
                             const float* __restrict__ Wk, const float* __restrict__ dq) {
    int idx = blockIdx.x * blockDim.x + threadIdx.x;     // 65536 threads
    if (idx >= 65536) return;
    int n = idx >> 8, k = idx & 255;
    g_WE [n*256 + k]        = __float2half(We[k*256 + n]);
    g_WQK[n*256 + k]        = __float2half(Wq[k*256 + n]);
    g_WQK[(256+n)*256 + k]  = __float2half(Wk[k*256 + n]);
    if (n < 16) g_DQ[n*256 + k] = (n < NDROP) ? __float2half(dq[n*256 + k]) : __float2half(0.f);
}

__global__ void prep_map(const void* __restrict__ rawp, const void* __restrict__ polp) {
    int j = blockIdx.x * blockDim.x + threadIdx.x;
    if (j >= NPOL) return;
    const int* r32 = (const int*)rawp;
    // raw indices are sorted distinct nonneg: if int64 little-endian, odd 32-bit words are 0;
    // if int32, r32[1],r32[3],... are >=1. Deterministic dtype detection.
    bool is64 = (r32[1] == 0 && r32[3] == 0 && r32[5] == 0 && r32[7] == 0);
    long long rv, pv;
    if (is64) { rv = ((const long long*)rawp)[j]; pv = ((const long long*)polp)[j]; }
    else      { rv = r32[j];                      pv = ((const int*)polp)[j]; }
    g_MAP[(int)pv] = (int)rv;
}

// ---------------- GEMM 1: PE = mish(X @ We + be) ----------------
// M=331776 (grid.x*128), N=256 (full), K=256. 512 threads, warp tile 32x64.
__global__ void __launch_bounds__(512, 1) k_pe(const float* __restrict__ X, const float* __restrict__ be) {
    extern __shared__ char sm[];
    uint32_t sbase = (uint32_t)__cvta_generic_to_shared(sm);
    const uint32_t OFF_B = 16384;              // A: [128][64]h = 16KB, B: [256][64]h = 32KB
    int tid = threadIdx.x, lane = tid & 31, w = tid >> 5;
    int wm = w >> 2, wn = w & 3;
    int m0 = blockIdx.x * 128;

    float acc[2][8][4] = {};

    for (int kk = 0; kk < 256; kk += 64) {
        #pragma unroll
        for (int t = 0; t < 2; ++t) {          // A tile: fp32 -> fp16 convert
            int idx = tid + t * 512; int r = idx >> 3, c = idx & 7;
            const float4* p = (const float4*)(X + (size_t)(m0 + r) * 256 + kk + c * 8);
            float4 f0 = p[0], f1 = p[1];
            uint4 u; u.x = pack2(f0.x, f0.y); u.y = pack2(f0.z, f0.w);
                     u.z = pack2(f1.x, f1.y); u.w = pack2(f1.z, f1.w);
            *(uint4*)(sm + swz128((uint32_t)(r * 128 + c * 16))) = u;
        }
        #pragma unroll
        for (int t = 0; t < 4; ++t) {          // B tile: weights fp16 (transposed layout)
            int idx = tid + t * 512; int r = idx >> 3, c = idx & 7;
            uint4 u = *(const uint4*)&g_WE[(size_t)r * 256 + kk + c * 8];
            *(uint4*)(sm + OFF_B + swz128((uint32_t)(r * 128 + c * 16))) = u;
        }
        __syncthreads();
        #pragma unroll
        for (int ks = 0; ks < 4; ++ks) {
            uint32_t a[2][4];
            #pragma unroll
            for (int i = 0; i < 2; ++i) {
                uint32_t off = swz128((uint32_t)((wm*32 + i*16 + (lane & 15)) * 128 + ks*32 + ((lane >> 4) << 4)));
                ldsm4(a[i][0], a[i][1], a[i][2], a[i][3], sbase + off);
            }
            #pragma unroll
            for (int j2 = 0; j2 < 4; ++j2) {
                uint32_t b0, b1, b2, b3;
                uint32_t off = swz128((uint32_t)((wn*64 + j2*16 + (lane & 7) + ((lane >> 4) << 3)) * 128
                                                 + ks*32 + (((lane >> 3) & 1) << 4)));
                ldsm4(b0, b1, b2, b3, sbase + OFF_B + off);
                #pragma unroll
                for (int i = 0; i < 2; ++i) {
                    mma16816(acc[i][2*j2],   a[i][0], a[i][1], a[i][2], a[i][3], b0, b1);
                    mma16816(acc[i][2*j2+1], a[i][0], a[i][1], a[i][2], a[i][3], b2, b3);
                }
            }
        }
        __syncthreads();
    }
    // epilogue: + bias, mish, -> fp16
    int rbase = m0 + wm * 32 + (lane >> 2);
    int cbase = wn * 64 + (lane & 3) * 2;
    #pragma unroll
    for (int i = 0; i < 2; ++i) {
        #pragma unroll
        for (int j = 0; j < 8; ++j) {
            int col = cbase + j * 8;
            float b0 = __ldg(be + col), b1 = __ldg(be + col + 1);
            int row = rbase + i * 16;
            float v0 = mishf(acc[i][j][0] + b0), v1 = mishf(acc[i][j][1] + b1);
            *(__half2*)&g_PE[(size_t)row * 256 + col] = __floats2half2_rn(v0, v1);
            float v2 = mishf(acc[i][j][2] + b0), v3 = mishf(acc[i][j][3] + b1);
            *(__half2*)&g_PE[(size_t)(row + 8) * 256 + col] = __floats2half2_rn(v2, v3);
        }
    }
}

// ---------------- GEMM 2: [Q|K] = PE @ [Wq|Wk] + [bq|bk] ----------------
__global__ void __launch_bounds__(512, 1) k_qk(const float* __restrict__ bq, const float* __restrict__ bk) {
    extern __shared__ char sm[];
    uint32_t sbase = (uint32_t)__cvta_generic_to_shared(sm);
    const uint32_t OFF_B = 16384;
    int tid = threadIdx.x, lane = tid & 31, w = tid >> 5;
    int wm = w >> 2, wn = w & 3;
    int m0 = blockIdx.x * 128;
    int n0 = blockIdx.y << 8;                 // 0 (Q) or 256 (K)

    float acc[2][8][4] = {};

    for (int kk = 0; kk < 256; kk += 64) {
        #pragma unroll
        for (int t = 0; t < 2; ++t) {          // A tile: PE fp16
            int idx = tid + t * 512; int r = idx >> 3, c = idx & 7;
            uint4 u = *(const uint4*)&g_PE[(size_t)(m0 + r) * 256 + kk + c * 8];
            *(uint4*)(sm + swz128((uint32_t)(r * 128 + c * 16))) = u;
        }
        #pragma unroll
        for (int t = 0; t < 4; ++t) {          // B tile
            int idx = tid + t * 512; int r = idx >> 3, c = idx & 7;
            uint4 u = *(const uint4*)&g_WQK[(size_t)(n0 + r) * 256 + kk + c * 8];
            *(uint4*)(sm + OFF_B + swz128((uint32_t)(r * 128 + c * 16))) = u;
        }
        __syncthreads();
        #pragma unroll
        for (int ks = 0; ks < 4; ++ks) {
            uint32_t a[2][4];
            #pragma unroll
            for (int i = 0; i < 2; ++i) {
                uint32_t off = swz128((uint32_t)((wm*32 + i*16 + (lane & 15)) * 128 + ks*32 + ((lane >> 4) << 4)));
                ldsm4(a[i][0], a[i][1], a[i][2], a[i][3], sbase + off);
            }
            #pragma unroll
            for (int j2 = 0; j2 < 4; ++j2) {
                uint32_t b0, b1, b2, b3;
                uint32_t off = swz128((uint32_t)((wn*64 + j2*16 + (lane & 7) + ((lane >> 4) << 3)) * 128
                                                 + ks*32 + (((lane >> 3) & 1) << 4)));
                ldsm4(b0, b1, b2, b3, sbase + OFF_B + off);
                #pragma unroll
                for (int i = 0; i < 2; ++i) {
                    mma16816(acc[i][2*j2],   a[i][0], a[i][1], a[i][2], a[i][3], b0, b1);
                    mma16816(acc[i][2*j2+1], a[i][0], a[i][1], a[i][2], a[i][3], b2, b3);
                }
            }
        }
        __syncthreads();
    }
    int rbase = m0 + wm * 32 + (lane >> 2);
    int cbase = wn * 64 + (lane & 3) * 2;
    #pragma unroll
    for (int i = 0; i < 2; ++i) {
        #pragma unroll
        for (int j = 0; j < 8; ++j) {
            int coln = n0 + cbase + j * 8;     // global n in [0,512)
            float b0 = (coln < 256) ? __ldg(bq + coln) : __ldg(bk + coln - 256);
            float b1 = (coln + 1 < 256) ? __ldg(bq + coln + 1) : __ldg(bk + coln + 1 - 256);
            int row = rbase + i * 16;
            *(__half2*)&g_QK[(size_t)row * 512 + coln] =
                __floats2half2_rn(acc[i][j][0] + b0, acc[i][j][1] + b1);
            *(__half2*)&g_QK[(size_t)(row + 8) * 512 + coln] =
                __floats2half2_rn(acc[i][j][2] + b0, acc[i][j][3] + b1);
        }
    }
}

// ---------------- attention + promo + drop + gather (one CTA per batch) ----------------
#define OFF_Q     0u
#define OFF_K     49152u           // 96 rows * 512B
#define OFF_DQ    98304u           // 16 rows * 512B
#define OFF_BOARD 106496u          // 96*96 fp32
#define OFF_DROP  143360u          // 16*96 fp32
#define OFF_WP    149504u          // 256 fp32
#define OFF_KWP   150528u          // 96 fp32
#define SMEM_ATTN 150912u

__global__ void __launch_bounds__(256, 1) k_attn(const float* __restrict__ Wp,
                                                 const float* __restrict__ bp,
                                                 float* __restrict__ out) {
    extern __shared__ char sm[];
    uint32_t sbase = (uint32_t)__cvta_generic_to_shared(sm);
    int tid = threadIdx.x, lane = tid & 31, w = tid >> 5;
    int b = blockIdx.x;
    size_t b81 = (size_t)b * 81;

    // load Q (81x256), K (81x256), DQ (16x256) into swizzled smem
    for (int idx = tid; idx < 81 * 32; idx += 256) {
        int r = idx >> 5, c = idx & 31;
        uint4 v = *(const uint4*)&g_QK[(b81 + r) * 512 + c * 8];
        *(uint4*)(sm + swz512(OFF_Q + (uint32_t)(r * 512 + c * 16))) = v;
    }
    for (int idx = tid; idx < 81 * 32; idx += 256) {
        int r = idx >> 5, c = idx & 31;
        uint4 v = *(const uint4*)&g_QK[(b81 + r) * 512 + 256 + c * 8];
        *(uint4*)(sm + swz512(OFF_K + (uint32_t)(r * 512 + c * 16))) = v;
    }
    for (int idx = tid; idx < 16 * 32; idx += 256) {
        int r = idx >> 5, c = idx & 31;
        uint4 v = *(const uint4*)&g_DQ[(size_t)r * 256 + c * 8];
        *(uint4*)(sm + swz512(OFF_DQ + (uint32_t)(r * 512 + c * 16))) = v;
    }
    if (tid < 64) ((float4*)(sm + OFF_WP))[tid] = ((const float4*)Wp)[tid];
    __syncthreads();

    if (w < 7) {
        // warps 0-5: board rows 16w..16w+15;  warp 6: drop queries (16 rows)
        float acc[12][4] = {};
        uint32_t abase = (w < 6) ? (OFF_Q + (uint32_t)(16 * w) * 512) : OFF_DQ;
        uint32_t aoff0 = abase + (uint32_t)(lane & 15) * 512 + ((uint32_t)(lane >> 4) << 4);
        uint32_t boff0 = OFF_K + (uint32_t)((lane & 7) + ((lane >> 4) << 3)) * 512
                         + (((uint32_t)(lane >> 3) & 1) << 4);
        #pragma unroll
        for (int ks = 0; ks < 16; ++ks) {
            uint32_t a0, a1, a2, a3;
            ldsm4(a0, a1, a2, a3, sbase + swz512(aoff0 + ks * 32));
            #pragma unroll
            for (int j2 = 0; j2 < 6; ++j2) {
                uint32_t b0, b1, b2, b3;
                ldsm4(b0, b1, b2, b3, sbase + swz512(boff0 + (uint32_t)j2 * 16 * 512 + ks * 32));
                mma16816(acc[2*j2],   a0, a1, a2, a3, b0, b1);
                mma16816(acc[2*j2+1], a0, a1, a2, a3, b2, b3);
            }
        }
        float* dst = (w < 6) ? ((float*)(sm + OFF_BOARD) + 16 * w * 96) : (float*)(sm + OFF_DROP);
        int rl = lane >> 2, cl = (lane & 3) * 2;
        #pragma unroll
        for (int j = 0; j < 12; ++j) {
            int col = j * 8 + cl;
            dst[rl * 96 + col]           = acc[j][0] * SCALE;
            dst[rl * 96 + col + 1]       = acc[j][1] * SCALE;
            dst[(rl + 8) * 96 + col]     = acc[j][2] * SCALE;
            dst[(rl + 8) * 96 + col + 1] = acc[j][3] * SCALE;
        }
    } else {
        // warp 7: kwp[k] = K[k,:] . Wp + bp
        const float* WpS = (const float*)(sm + OFF_WP);
        float* kwpS = (float*)(sm + OFF_KWP);
        float bpv = __ldg(bp);
        for (int r = 0; r < 81; ++r) {
            uint4 v = *(const uint4*)(sm + swz512(OFF_K + (uint32_t)(r * 512 + lane * 16)));
            const __half* h = (const __half*)&v;
            float s = 0.f;
            #pragma unroll
            for (int i = 0; i < 8; ++i) s += __half2float(h[i]) * WpS[lane * 8 + i];
            #pragma unroll
            for (int o = 16; o; o >>= 1) s += __shfl_xor_sync(0xffffffffu, s, o);
            if (lane == 0) kwpS[r] = s + bpv;
        }
    }
    __syncthreads();

    // permuted gather, coalesced output
    const float* boardS = (const float*)(sm + OFF_BOARD);
    const float* dropS  = (const float*)(sm + OFF_DROP);
    const float* kwpS   = (const float*)(sm + OFF_KWP);
    for (int p = tid; p < NPOL; p += 256) {
        int r = g_MAP[p];
        float v;
        if (r < 6561) {
            int q = r / 81, k = r - q * 81;
            v = boardS[q * 96 + k];
        } else if (r < 13122) {
            int r2 = r - 6561;
            int q = r2 / 81, k = r2 - q * 81;
            v = boardS[q * 96 + k] + kwpS[k];
        } else {
            int r3 = r - 13122;
            int n = r3 / 81, k = r3 - n * 81;
            v = dropS[n * 96 + k];
        }
        out[(size_t)b * NPOL + p] = v;
    }
}

// ---------------- launch ----------------
extern "C" void kernel_launch(void* const* d_in, const int* in_sizes, int n_in,
                              void* d_out, int out_size) {
    const float* x   = (const float*)d_in[0];
    const float* We  = (const float*)d_in[1];
    const float* be  = (const float*)d_in[2];
    const float* Wq  = (const float*)d_in[3];
    const float* bq  = (const float*)d_in[4];
    const float* Wk  = (const float*)d_in[5];
    const float* bk  = (const float*)d_in[6];
    const float* Wp  = (const float*)d_in[7];
    const float* bp  = (const float*)d_in[8];
    const float* dq  = (const float*)d_in[9];
    const void*  raw = d_in[10];
    const void*  pol = d_in[11];
    float* out = (float*)d_out;

    cudaFuncSetAttribute(k_attn, cudaFuncAttributeMaxDynamicSharedMemorySize, SMEM_ATTN);

    prep_weights<<<256, 256>>>(We, Wq, Wk, dq);
    prep_map<<<16, 256>>>(raw, pol);
    k_pe<<<MROWS / 128, 512, 49152>>>(x, be);
    k_qk<<<dim3(MROWS / 128, 2), 512, 49152>>>(bq, bk);
    k_attn<<<NB, 256, SMEM_ATTN>>>(Wp, bp, out);
}

// round 2
// speedup vs baseline: 1.3384x; 1.3384x over previous
#include <cuda_runtime.h>
#include <cuda_fp16.h>
#include <cstdint>

// ---------------- problem constants ----------------
#define NB     4096
#define SQ     81
#define DIM    256
#define NPOL   3849
#define NDROP  7
#define SCALE  0.0625f          // 1/sqrt(256)

// ---------------- device scratch (no allocs allowed) ----------------
__device__ __align__(128) __half g_WE [256*256];             // We^T  [n][k]
__device__ __align__(128) __half g_WQK[512*256];             // [Wq^T ; Wk^T] [n][k]
__device__ __align__(128) __half g_DQ [16*256];              // drop queries, zero padded
__device__ int g_MAP[NPOL];                                   // out slot p -> raw index

// ---------------- smem layout (bytes) ----------------
#define OFF_SB    0u            // B tiles: 2 x [256][64]h = 2 x 32768
#define OFF_PE    65536u        // 96 x 512B
#define OFF_SQ    114688u       // 96 x 512B (first holds X fp16, then Q)
#define OFF_SK    163840u       // 96 x 512B
#define OFF_DQ    212992u       // 16 x 512B
#define OFF_WP    221184u       // 256 f32
#define OFF_KWP   222208u       // 96 f32 (padded)
#define SMEM_TOT  222720u
// overlays on the B-tile region (free after GEMMs):
#define OFF_BOARD 0u            // 96*96 f32 = 36864
#define OFF_DROP  36864u        // 16*96 f32 = 6144

// ---------------- helpers ----------------
__device__ __forceinline__ uint32_t swz128(uint32_t o) { return o ^ ((o >> 3) & 0x70); }
__device__ __forceinline__ uint32_t swz512(uint32_t o) { return o ^ ((o >> 5) & 0x70); }

__device__ __forceinline__ uint32_t pack2(float a, float b) {
    __half2 h = __floats2half2_rn(a, b);
    return *reinterpret_cast<uint32_t*>(&h);
}

__device__ __forceinline__ void ldsm4(uint32_t& r0, uint32_t& r1, uint32_t& r2, uint32_t& r3, uint32_t addr) {
    asm volatile("ldmatrix.sync.aligned.m8n8.x4.shared.b16 {%0,%1,%2,%3}, [%4];\n"
                 : "=r"(r0), "=r"(r1), "=r"(r2), "=r"(r3) : "r"(addr));
}

__device__ __forceinline__ void mma16816(float* c, uint32_t a0, uint32_t a1, uint32_t a2, uint32_t a3,
                                         uint32_t b0, uint32_t b1) {
    asm volatile("mma.sync.aligned.m16n8k16.row.col.f32.f16.f16.f32 "
                 "{%0,%1,%2,%3},{%4,%5,%6,%7},{%8,%9},{%0,%1,%2,%3};\n"
                 : "+f"(c[0]), "+f"(c[1]), "+f"(c[2]), "+f"(c[3])
                 : "r"(a0), "r"(a1), "r"(a2), "r"(a3), "r"(b0), "r"(b1));
}

__device__ __forceinline__ float mishf(float v) {
    float sp = (v > 15.f) ? v : log1pf(expf(v));
    return v * tanhf(sp);
}

__device__ __forceinline__ void cp_async16(uint32_t dst, const void* src) {
    asm volatile("cp.async.cg.shared.global [%0], [%1], 16;\n" :: "r"(dst), "l"(src));
}
__device__ __forceinline__ void cp_commit() { asm volatile("cp.async.commit_group;\n" ::: "memory"); }
template<int N> __device__ __forceinline__ void cp_wait() {
    asm volatile("cp.async.wait_group %0;\n" :: "n"(N) : "memory");
}

// ---------------- prep kernels ----------------
__global__ void prep_weights(const float* __restrict__ We, const float* __restrict__ Wq,
                             const float* __restrict__ Wk, const float* __restrict__ dq) {
    int idx = blockIdx.x * blockDim.x + threadIdx.x;     // 65536 threads
    if (idx >= 65536) return;
    int n = idx >> 8, k = idx & 255;
    g_WE [n*256 + k]        = __float2half(We[k*256 + n]);
    g_WQK[n*256 + k]        = __float2half(Wq[k*256 + n]);
    g_WQK[(256+n)*256 + k]  = __float2half(Wk[k*256 + n]);
    if (n < 16) g_DQ[n*256 + k] = (n < NDROP) ? __float2half(dq[n*256 + k]) : __float2half(0.f);
}

__global__ void prep_map(const void* __restrict__ rawp, const void* __restrict__ polp) {
    int j = blockIdx.x * blockDim.x + threadIdx.x;
    if (j >= NPOL) return;
    const int* r32 = (const int*)rawp;
    bool is64 = (r32[1] == 0 && r32[3] == 0 && r32[5] == 0 && r32[7] == 0);
    long long rv, pv;
    if (is64) { rv = ((const long long*)rawp)[j]; pv = ((const long long*)polp)[j]; }
    else      { rv = r32[j];                      pv = ((const int*)polp)[j]; }
    g_MAP[(int)pv] = (int)rv;
}

// ---------------- fused per-batch GEMM helper ----------------
// A: 96x256 fp16 at smem offset aOff (512B rows, swz512).
// B: W[256][256] fp16 global (row-major [n][k]), streamed as 4 x [256][64] chunks
//    into double-buffered smem at OFF_SB (128B rows, swz128) via cp.async.
// Warp grid 3M x 4N (12 warps). Warp tile 32x64. Output (after bias [+mish])
// stored fp16 to smem offset dOff (512B rows, swz512).
template<bool MISH>
__device__ __forceinline__ void gemm_tile(char* sm, uint32_t sbase, uint32_t aOff,
                                          const __half* __restrict__ W,
                                          uint32_t dOff, const float* __restrict__ bias,
                                          int tid) {
    int lane = tid & 31, w = tid >> 5;
    int wm = w >> 2, wn = w & 3;                    // wm 0..2, wn 0..3
    float acc[2][8][4] = {};

    // preload chunk 0
    for (int i = tid; i < 2048; i += 384) {
        int r = i >> 3, c = i & 7;
        cp_async16(sbase + OFF_SB + swz128((uint32_t)(r * 128 + c * 16)), W + r * 256 + c * 8);
    }
    cp_commit();

    #pragma unroll
    for (int ck = 0; ck < 4; ++ck) {
        if (ck < 3) {
            int kk = (ck + 1) * 64;
            uint32_t bufo = (uint32_t)((ck + 1) & 1) * 32768u;
            for (int i = tid; i < 2048; i += 384) {
                int r = i >> 3, c = i & 7;
                cp_async16(sbase + OFF_SB + bufo + swz128((uint32_t)(r * 128 + c * 16)),
                           W + r * 256 + kk + c * 8);
            }
            cp_commit();
            cp_wait<1>();
        } else {
            cp_wait<0>();
        }
        __syncthreads();

        uint32_t bO = OFF_SB + (uint32_t)(ck & 1) * 32768u;
        uint32_t kkb = (uint32_t)ck * 128u;          // chunk byte offset within A rows
        #pragma unroll
        for (int ks = 0; ks < 4; ++ks) {
            uint32_t a[2][4];
            #pragma unroll
            for (int i = 0; i < 2; ++i) {
                uint32_t off = swz512((uint32_t)((wm*32 + i*16 + (lane & 15)) * 512
                                                 + kkb + ks*32 + ((lane >> 4) << 4)));
                ldsm4(a[i][0], a[i][1], a[i][2], a[i][3], sbase + aOff + off);
            }
            #pragma unroll
            for (int j2 = 0; j2 < 4; ++j2) {
                uint32_t b0, b1, b2, b3;
                uint32_t off = swz128((uint32_t)((wn*64 + j2*16 + (lane & 7) + ((lane >> 4) << 3)) * 128
                                                 + ks*32 + (((lane >> 3) & 1) << 4)));
                ldsm4(b0, b1, b2, b3, sbase + bO + off);
                #pragma unroll
                for (int i = 0; i < 2; ++i) {
                    mma16816(acc[i][2*j2],   a[i][0], a[i][1], a[i][2], a[i][3], b0, b1);
                    mma16816(acc[i][2*j2+1], a[i][0], a[i][1], a[i][2], a[i][3], b2, b3);
                }
            }
        }
        __syncthreads();
    }

    // epilogue -> smem fp16 (swz512 layout)
    int rbase = wm * 32 + (lane >> 2);
    int cbase = wn * 64 + (lane & 3) * 2;
    #pragma unroll
    for (int i = 0; i < 2; ++i) {
        #pragma unroll
        for (int j = 0; j < 8; ++j) {
            int col = cbase + j * 8;
            float b0 = __ldg(bias + col), b1 = __ldg(bias + col + 1);
            int row = rbase + i * 16;
            float v0 = acc[i][j][0] + b0, v1 = acc[i][j][1] + b1;
            float v2 = acc[i][j][2] + b0, v3 = acc[i][j][3] + b1;
            if (MISH) { v0 = mishf(v0); v1 = mishf(v1); v2 = mishf(v2); v3 = mishf(v3); }
            *(__half2*)(sm + dOff + swz512((uint32_t)(row * 512 + col * 2))) = __floats2half2_rn(v0, v1);
            *(__half2*)(sm + dOff + swz512((uint32_t)((row + 8) * 512 + col * 2))) = __floats2half2_rn(v2, v3);
        }
    }
}

// ---------------- fused kernel: one CTA per batch ----------------
__global__ void __launch_bounds__(384, 1) k_fused(const float* __restrict__ X,
                                                  const float* __restrict__ be,
                                                  const float* __restrict__ bq,
                                                  const float* __restrict__ bk,
                                                  const float* __restrict__ Wp,
                                                  const float* __restrict__ bp,
                                                  float* __restrict__ out) {
    extern __shared__ char sm[];
    uint32_t sbase = (uint32_t)__cvta_generic_to_shared(sm);
    int tid = threadIdx.x, lane = tid & 31, w = tid >> 5;
    int b = blockIdx.x;

    // ---- phase 0: X (81x256 f32 -> fp16, zero-pad to 96) into sQ; DQ; Wp ----
    for (int idx = tid; idx < 3072; idx += 384) {
        int r = idx >> 5, c = idx & 31;
        uint4 u;
        if (r < 81) {
            const float4* p = (const float4*)(X + ((size_t)b * 81 + r) * 256 + c * 8);
            float4 f0 = p[0], f1 = p[1];
            u.x = pack2(f0.x, f0.y); u.y = pack2(f0.z, f0.w);
            u.z = pack2(f1.x, f1.y); u.w = pack2(f1.z, f1.w);
        } else {
            u = make_uint4(0u, 0u, 0u, 0u);
        }
        *(uint4*)(sm + OFF_SQ + swz512((uint32_t)(r * 512 + c * 16))) = u;
    }
    for (int idx = tid; idx < 512; idx += 384) {
        int r = idx >> 5, c = idx & 31;
        uint4 v = *(const uint4*)&g_DQ[(size_t)r * 256 + c * 8];
        *(uint4*)(sm + OFF_DQ + swz512((uint32_t)(r * 512 + c * 16))) = v;
    }
    if (tid < 64) ((float4*)(sm + OFF_WP))[tid] = ((const float4*)Wp)[tid];
    // no explicit sync needed: first compute in gemm_tile is preceded by __syncthreads

    // ---- phase 1: PE = mish(XH @ We^T + be) -> sPE ----
    gemm_tile<true >(sm, sbase, OFF_SQ, g_WE,           OFF_PE, be, tid);
    // ---- phase 2: Q = PE @ Wq^T + bq -> sQ (overwrites XH); K -> sK ----
    gemm_tile<false>(sm, sbase, OFF_PE, g_WQK,          OFF_SQ, bq, tid);
    gemm_tile<false>(sm, sbase, OFF_PE, g_WQK + 65536,  OFF_SK, bk, tid);
    __syncthreads();

    // ---- phase 3: attention board / drop / promo offset ----
    if (w < 7) {
        // warps 0-5: board rows 16w..16w+15; warp 6: drop queries (16 rows)
        float acc[12][4] = {};
        uint32_t abase = (w < 6) ? (OFF_SQ + (uint32_t)(16 * w) * 512) : OFF_DQ;
        uint32_t aoff0 = abase + (uint32_t)(lane & 15) * 512 + ((uint32_t)(lane >> 4) << 4);
        uint32_t boff0 = OFF_SK + (uint32_t)((lane & 7) + ((lane >> 4) << 3)) * 512
                         + (((uint32_t)(lane >> 3) & 1) << 4);
        #pragma unroll
        for (int ks = 0; ks < 16; ++ks) {
            uint32_t a0, a1, a2, a3;
            ldsm4(a0, a1, a2, a3, sbase + swz512(aoff0 + ks * 32) + (aoff0 & 0xFFFFF000u) * 0u);
            // note: swz512 applied to full offset (region bases are 4KB-aligned, commute)
            #pragma unroll
            for (int j2 = 0; j2 < 6; ++j2) {
                uint32_t b0, b1, b2, b3;
                ldsm4(b0, b1, b2, b3, sbase + swz512(boff0 + (uint32_t)j2 * 16 * 512 + ks * 32));
                mma16816(acc[2*j2],   a0, a1, a2, a3, b0, b1);
                mma16816(acc[2*j2+1], a0, a1, a2, a3, b2, b3);
            }
        }
        float* dst = (w < 6) ? ((float*)(sm + OFF_BOARD) + 16 * w * 96) : (float*)(sm + OFF_DROP);
        int rl = lane >> 2, cl = (lane & 3) * 2;
        #pragma unroll
        for (int j = 0; j < 12; ++j) {
            int col = j * 8 + cl;
            dst[rl * 96 + col]           = acc[j][0] * SCALE;
            dst[rl * 96 + col + 1]       = acc[j][1] * SCALE;
            dst[(rl + 8) * 96 + col]     = acc[j][2] * SCALE;
            dst[(rl + 8) * 96 + col + 1] = acc[j][3] * SCALE;
        }
    } else if (w == 7) {
        // kwp[k] = K[k,:] . Wp + bp
        const float* WpS = (const float*)(sm + OFF_WP);
        float* kwpS = (float*)(sm + OFF_KWP);
        float bpv = __ldg(bp);
        for (int r = 0; r < 81; ++r) {
            uint4 v = *(const uint4*)(sm + swz512(OFF_SK + (uint32_t)(r * 512 + lane * 16)));
            const __half* h = (const __half*)&v;
            float s = 0.f;
            #pragma unroll
            for (int i = 0; i < 8; ++i) s += __half2float(h[i]) * WpS[lane * 8 + i];
            #pragma unroll
            for (int o = 16; o; o >>= 1) s += __shfl_xor_sync(0xffffffffu, s, o);
            if (lane == 0) kwpS[r] = s + bpv;
        }
    }
    __syncthreads();

    // ---- phase 4: permuted gather, coalesced output ----
    const float* boardS = (const float*)(sm + OFF_BOARD);
    const float* dropS  = (const float*)(sm + OFF_DROP);
    const float* kwpS   = (const float*)(sm + OFF_KWP);
    for (int p = tid; p < NPOL; p += 384) {
        int r = g_MAP[p];
        float v;
        if (r < 6561) {
            int q = r / 81, k = r - q * 81;
            v = boardS[q * 96 + k];
        } else if (r < 13122) {
            int r2 = r - 6561;
            int q = r2 / 81, k = r2 - q * 81;
            v = boardS[q * 96 + k] + kwpS[k];
        } else {
            int r3 = r - 13122;
            int n = r3 / 81, k = r3 - n * 81;
            v = dropS[n * 96 + k];
        }
        out[(size_t)b * NPOL + p] = v;
    }
}

// ---------------- launch ----------------
extern "C" void kernel_launch(void* const* d_in, const int* in_sizes, int n_in,
                              void* d_out, int out_size) {
    const float* x   = (const float*)d_in[0];
    const float* We  = (const float*)d_in[1];
    const float* be  = (const float*)d_in[2];
    const float* Wq  = (const float*)d_in[3];
    const float* bq  = (const float*)d_in[4];
    const float* Wk  = (const float*)d_in[5];
    const float* bk  = (const float*)d_in[6];
    const float* Wp  = (const float*)d_in[7];
    const float* bp  = (const float*)d_in[8];
    const float* dq  = (const float*)d_in[9];
    const void*  raw = d_in[10];
    const void*  pol = d_in[11];
    float* out = (float*)d_out;

    cudaFuncSetAttribute(k_fused, cudaFuncAttributeMaxDynamicSharedMemorySize, SMEM_TOT);

    prep_weights<<<256, 256>>>(We, Wq, Wk, dq);
    prep_map<<<16, 256>>>(raw, pol);
    k_fused<<<NB, 384, SMEM_TOT>>>(x, be, bq, bk, Wp, bp, out);
}

// round 4
// speedup vs baseline: 2.2554x; 1.6851x over previous
#include <cuda_runtime.h>
#include <cuda_fp16.h>
#include <cstdint>

// ---------------- problem constants ----------------
#define NB     4096
#define NPOL   3849
#define NDROP  7
#define SCALE  0.0625f          // 1/sqrt(256)

// ---------------- smem layout (bytes) ----------------
// PE region: 81 rows x 512B written (reads up to row 95 spill into S region = zeros)
// S  region: 91 rows x 512B written (S rows 0-80 + S_ext rows 81-90); reads to row 95 spill into B
// B  region: 2 x 32KB double-buffered weight chunks [256n][64k] fp16 SW128
#define OFF_PE   0u
#define OFF_S    41472u         // 81*512
#define OFF_B    88064u         // 41472 + 91*512
#define SMEM_TOT 153600u        // 88064 + 2*32768
// board staging (f32 [96][96]) overlays S region after GEMM3

// ---------------- device scratch ----------------
__device__ __align__(128) __half g_WE  [256*256];   // We^T  [n][k]
__device__ __align__(128) __half g_W2  [256*256];   // B for GEMM2: SCALE*(Wq Wk^T)^T  [n][k]
__device__ __align__(128) __half g_SEXT[10*256];    // S_ext rows 81..90
__device__ float g_CONST[16];                        // [0]=cQK [1..7]=cdrop [8]=ckwp
__device__ int g_MAP[NPOL];

// ---------------- helpers ----------------
__device__ __forceinline__ uint32_t swz128(uint32_t o) { return o ^ ((o >> 3) & 0x70); }
__device__ __forceinline__ uint32_t swz512(uint32_t o) { return o ^ ((o >> 5) & 0x70); }

__device__ __forceinline__ uint32_t pack2(float a, float b) {
    __half2 h = __floats2half2_rn(a, b);
    return *reinterpret_cast<uint32_t*>(&h);
}

__device__ __forceinline__ void ldsm4(uint32_t& r0, uint32_t& r1, uint32_t& r2, uint32_t& r3, uint32_t addr) {
    asm volatile("ldmatrix.sync.aligned.m8n8.x4.shared.b16 {%0,%1,%2,%3}, [%4];\n"
                 : "=r"(r0), "=r"(r1), "=r"(r2), "=r"(r3) : "r"(addr));
}

__device__ __forceinline__ void mma16816(float* c, uint32_t a0, uint32_t a1, uint32_t a2, uint32_t a3,
                                         uint32_t b0, uint32_t b1) {
    asm volatile("mma.sync.aligned.m16n8k16.row.col.f32.f16.f16.f32 "
                 "{%0,%1,%2,%3},{%4,%5,%6,%7},{%8,%9},{%0,%1,%2,%3};\n"
                 : "+f"(c[0]), "+f"(c[1]), "+f"(c[2]), "+f"(c[3])
                 : "r"(a0), "r"(a1), "r"(a2), "r"(a3), "r"(b0), "r"(b1));
}

__device__ __forceinline__ float mishf(float v) {
    float e  = __expf(v);
    float sp = (v > 15.f) ? v : __logf(1.f + e);     // softplus
    float z  = __expf(-2.f * sp);
    float t  = __fdividef(1.f - z, 1.f + z);          // tanh(sp)
    return v * t;
}

__device__ __forceinline__ void cp_async16(uint32_t dst, const void* src) {
    asm volatile("cp.async.cg.shared.global [%0], [%1], 16;\n" :: "r"(dst), "l"(src));
}
__device__ __forceinline__ void cp_commit() { asm volatile("cp.async.commit_group;\n" ::: "memory"); }
template<int N> __device__ __forceinline__ void cp_wait() {
    asm volatile("cp.async.wait_group %0;\n" :: "n"(N) : "memory");
}

// ---------------- prep kernels ----------------
__global__ void prep_we(const float* __restrict__ We) {
    int idx = blockIdx.x * blockDim.x + threadIdx.x;
    if (idx >= 65536) return;
    int n = idx >> 8, k = idx & 255;
    g_WE[n*256 + k] = __float2half(We[k*256 + n]);
}

// g_W2[n][k] = SCALE * sum_o Wq[k,o] * Wk[n,o]
__global__ void prep_w2(const float* __restrict__ Wq, const float* __restrict__ Wk) {
    __shared__ float wkrow[256];
    int n = blockIdx.x, k = threadIdx.x;
    wkrow[k] = Wk[n*256 + k];
    __syncthreads();
    const float4* wq = (const float4*)(Wq + (size_t)k * 256);
    float s = 0.f;
    #pragma unroll 8
    for (int o = 0; o < 64; ++o) {
        float4 q = wq[o];
        s += q.x * wkrow[4*o] + q.y * wkrow[4*o+1] + q.z * wkrow[4*o+2] + q.w * wkrow[4*o+3];
    }
    g_W2[n*256 + k] = __float2half(s * SCALE);
}

// S_ext rows: t=0..6 -> SCALE*dq[t]·Wk^T ; t=7 -> Wk·Wp ; t=8 -> SCALE*Wk·bq ; t=9 -> SCALE*Wq·bk
__global__ void prep_small(const float* __restrict__ Wq, const float* __restrict__ Wk,
                           const float* __restrict__ Wp, const float* __restrict__ bq,
                           const float* __restrict__ bk, const float* __restrict__ dqm) {
    int j = blockIdx.x, lane = threadIdx.x;
    float acc[10];
    #pragma unroll
    for (int t = 0; t < 10; ++t) acc[t] = 0.f;
    for (int o = lane; o < 256; o += 32) {
        float wk = Wk[j*256 + o];
        float wq = Wq[j*256 + o];
        #pragma unroll
        for (int n = 0; n < 7; ++n) acc[n] += dqm[n*256 + o] * wk;
        acc[7] += wk * Wp[o];
        acc[8] += wk * bq[o];
        acc[9] += wq * bk[o];
    }
    #pragma unroll
    for (int t = 0; t < 10; ++t) {
        #pragma unroll
        for (int off = 16; off; off >>= 1) acc[t] += __shfl_xor_sync(0xffffffffu, acc[t], off);
    }
    if (lane == 0) {
        #pragma unroll
        for (int t = 0; t < 10; ++t) {
            float v = acc[t];
            if (t != 7) v *= SCALE;           // kwp row is unscaled
            g_SEXT[t*256 + j] = __float2half(v);
        }
    }
}

__global__ void prep_consts(const float* __restrict__ bq, const float* __restrict__ bk,
                            const float* __restrict__ Wp, const float* __restrict__ bp,
                            const float* __restrict__ dqm) {
    __shared__ float s[256];
    int t = threadIdx.x;
    float vals[9];
    vals[0] = bq[t] * bk[t];
    #pragma unroll
    for (int n = 0; n < 7; ++n) vals[1+n] = dqm[n*256 + t] * bk[t];
    vals[8] = bk[t] * Wp[t];
    #pragma unroll
    for (int r = 0; r < 9; ++r) {
        s[t] = vals[r]; __syncthreads();
        for (int st = 128; st; st >>= 1) { if (t < st) s[t] += s[t+st]; __syncthreads(); }
        float total = s[0]; __syncthreads();
        if (t == 0) {
            if (r == 0)      g_CONST[0] = total * SCALE;
            else if (r <= 7) g_CONST[r] = total * SCALE;
            else             g_CONST[8] = total + bp[0];
        }
    }
}

__global__ void prep_map(const void* __restrict__ rawp, const void* __restrict__ polp) {
    int j = blockIdx.x * blockDim.x + threadIdx.x;
    if (j >= NPOL) return;
    const int* r32 = (const int*)rawp;
    bool is64 = (r32[1] == 0 && r32[3] == 0 && r32[5] == 0 && r32[7] == 0);
    long long rv, pv;
    if (is64) { rv = ((const long long*)rawp)[j]; pv = ((const long long*)polp)[j]; }
    else      { rv = r32[j];                      pv = ((const int*)polp)[j]; }
    g_MAP[(int)pv] = (int)rv;
}

// ---------------- fused kernel pieces ----------------
__device__ __forceinline__ void prefetch_chunk(uint32_t sbase, const __half* __restrict__ W,
                                               int c, int buf, int tid) {
    #pragma unroll
    for (int t = 0; t < 6; ++t) {            // 2048 sites / 384 threads
        int i = tid + t * 384;
        if (i < 2048) {
            int r = i >> 3, col = i & 7;
            cp_async16(sbase + OFF_B + (uint32_t)buf * 32768u + swz128((uint32_t)(r*128 + col*16)),
                       W + (size_t)r * 256 + c * 64 + col * 8);
        }
    }
    cp_commit();
}

__device__ __forceinline__ void gemm_chunk(float acc[2][8][4], uint32_t sbase,
                                           int c, int buf, int lane, int wm, int wn) {
    uint32_t bO = OFF_B + (uint32_t)buf * 32768u;
    #pragma unroll
    for (int ks = 0; ks < 4; ++ks) {
        uint32_t a[2][4];
        #pragma unroll
        for (int i = 0; i < 2; ++i) {
            uint32_t off = swz512((uint32_t)((wm*32 + i*16 + (lane & 15)) * 512
                                             + c*128 + ks*32 + ((lane >> 4) << 4)));
            ldsm4(a[i][0], a[i][1], a[i][2], a[i][3], sbase + OFF_PE + off);
        }
        #pragma unroll
        for (int j2 = 0; j2 < 4; ++j2) {
            uint32_t b0, b1, b2, b3;
            uint32_t off = swz128((uint32_t)((wn*64 + j2*16 + (lane&7) + ((lane>>4)<<3)) * 128
                                             + ks*32 + (((lane>>3)&1)<<4)));
            ldsm4(b0, b1, b2, b3, sbase + bO + off);
            #pragma unroll
            for (int i = 0; i < 2; ++i) {
                mma16816(acc[i][2*j2],   a[i][0], a[i][1], a[i][2], a[i][3], b0, b1);
                mma16816(acc[i][2*j2+1], a[i][0], a[i][1], a[i][2], a[i][3], b2, b3);
            }
        }
    }
}

// chunk 0 must already be prefetched+committed
__device__ __forceinline__ void gemm_main(float acc[2][8][4], uint32_t sbase,
                                          const __half* __restrict__ W,
                                          int tid, int lane, int wm, int wn) {
    #pragma unroll
    for (int c = 0; c < 4; ++c) {
        if (c < 3) { prefetch_chunk(sbase, W, c+1, (c+1)&1, tid); cp_wait<1>(); }
        else       { cp_wait<0>(); }
        __syncthreads();
        gemm_chunk(acc, sbase, c, c&1, lane, wm, wn);
        __syncthreads();
    }
}

// ---------------- fused kernel: one CTA per batch ----------------
__global__ void __launch_bounds__(384, 1) k_fused(const float* __restrict__ X,
                                                  const float* __restrict__ be,
                                                  float* __restrict__ out) {
    extern __shared__ char sm[];
    uint32_t sbase = (uint32_t)__cvta_generic_to_shared(sm);
    int tid = threadIdx.x, lane = tid & 31, w = tid >> 5;
    int wm = w >> 2, wn = w & 3;             // GEMM1/2 warp grid 3m x 4n, tile 32x64
    int b = blockIdx.x;

    // ---- P0: prefetch We chunk0; X (81x256 f32->fp16, rows 81-95 zero) into PE region ----
    prefetch_chunk(sbase, g_WE, 0, 0, tid);
    for (int idx = tid; idx < 3072; idx += 384) {
        int r = idx >> 5, c = idx & 31;
        uint4 u;
        if (r < 81) {
            const float4* p = (const float4*)(X + ((size_t)b * 81 + r) * 256 + c * 8);
            float4 f0 = p[0], f1 = p[1];
            u.x = pack2(f0.x, f0.y); u.y = pack2(f0.z, f0.w);
            u.z = pack2(f1.x, f1.y); u.w = pack2(f1.z, f1.w);
        } else {
            u = make_uint4(0u, 0u, 0u, 0u);
        }
        *(uint4*)(sm + OFF_PE + swz512((uint32_t)(r * 512 + c * 16)));
        *(uint4*)(sm + OFF_PE + swz512((uint32_t)(r * 512 + c * 16))) = u;
    }

    // ---- GEMM1: PE = mish(X @ We^T + be), in place over X ----
    {
        float acc[2][8][4] = {};
        gemm_main(acc, sbase, g_WE, tid, lane, wm, wn);
        prefetch_chunk(sbase, g_W2, 0, 0, tid);      // overlap W2 chunk0 with mish epilogue
        int rbase = wm * 32 + (lane >> 2);
        int cbase = wn * 64 + (lane & 3) * 2;
        #pragma unroll
        for (int i = 0; i < 2; ++i) {
            #pragma unroll
            for (int j = 0; j < 8; ++j) {
                int col = cbase + j * 8;
                float b0 = __ldg(be + col), b1 = __ldg(be + col + 1);
                int row = rbase + i * 16;
                if (row < 81) {
                    float v0 = mishf(acc[i][j][0] + b0), v1 = mishf(acc[i][j][1] + b1);
                    *(uint32_t*)(sm + OFF_PE + swz512((uint32_t)(row * 512 + col * 2))) = pack2(v0, v1);
                }
                if (row + 8 < 81) {
                    float v2 = mishf(acc[i][j][2] + b0), v3 = mishf(acc[i][j][3] + b1);
                    *(uint32_t*)(sm + OFF_PE + swz512((uint32_t)((row + 8) * 512 + col * 2))) = pack2(v2, v3);
                }
            }
        }
    }

    // ---- GEMM2: S = PE @ W2 (fp16 -> S region rows 0-80), then S_ext rows 81-90 ----
    {
        float acc[2][8][4] = {};
        gemm_main(acc, sbase, g_W2, tid, lane, wm, wn);
        int rbase = wm * 32 + (lane >> 2);
        int cbase = wn * 64 + (lane & 3) * 2;
        #pragma unroll
        for (int i = 0; i < 2; ++i) {
            #pragma unroll
            for (int j = 0; j < 8; ++j) {
                int col = cbase + j * 8;
                int row = rbase + i * 16;
                if (row < 81)
                    *(uint32_t*)(sm + OFF_S + swz512((uint32_t)(row * 512 + col * 2))) =
                        pack2(acc[i][j][0], acc[i][j][1]);
                if (row + 8 < 81)
                    *(uint32_t*)(sm + OFF_S + swz512((uint32_t)((row + 8) * 512 + col * 2))) =
                        pack2(acc[i][j][2], acc[i][j][3]);
            }
        }
        // S_ext rows 81..90 from g_SEXT
        if (tid < 320) {
            int t = tid >> 5, c = tid & 31;
            uint4 v = *(const uint4*)&g_SEXT[t * 256 + c * 8];
            *(uint4*)(sm + OFF_S + swz512((uint32_t)((81 + t) * 512 + c * 16))) = v;
        }
    }
    __syncthreads();

    // ---- GEMM3: board_ext = S_ext @ PE^T  (96x96x256) ----
    float acc3[6][4] = {};
    {
        int wm3 = w >> 1, wn2 = w & 1;       // 6m x 2n, warp tile 16x48
        uint32_t aoff0 = (uint32_t)(wm3*16 + (lane & 15)) * 512 + ((uint32_t)(lane >> 4) << 4);
        uint32_t bn0 = (uint32_t)(wn2*48 + (lane & 7) + ((lane >> 4) << 3));
        #pragma unroll
        for (int ks = 0; ks < 16; ++ks) {
            uint32_t a0, a1, a2, a3;
            ldsm4(a0, a1, a2, a3, sbase + OFF_S + swz512(aoff0 + ks * 32));
            #pragma unroll
            for (int j2 = 0; j2 < 3; ++j2) {
                uint32_t b0, b1, b2, b3;
                uint32_t off = swz512((bn0 + (uint32_t)j2 * 16) * 512 + ks * 32
                                      + (((uint32_t)(lane >> 3) & 1) << 4));
                ldsm4(b0, b1, b2, b3, sbase + OFF_PE + off);
                mma16816(acc3[2*j2],   a0, a1, a2, a3, b0, b1);
                mma16816(acc3[2*j2+1], a0, a1, a2, a3, b2, b3);
            }
        }
    }
    __syncthreads();                          // all S/PE reads done -> safe to overwrite S with staging

    // ---- staging: board_ext f32 [96][96] over S region ----
    {
        int wm3 = w >> 1, wn2 = w & 1;
        float* stag = (float*)(sm + OFF_S);
        int rl = wm3 * 16 + (lane >> 2);
        int cl = wn2 * 48 + (lane & 3) * 2;
        #pragma unroll
        for (int j = 0; j < 6; ++j) {
            int col = cl + j * 8;
            stag[rl * 96 + col]           = acc3[j][0];
            stag[rl * 96 + col + 1]       = acc3[j][1];
            stag[(rl + 8) * 96 + col]     = acc3[j][2];
            stag[(rl + 8) * 96 + col + 1] = acc3[j][3];
        }
    }
    __syncthreads();

    // ---- permuted gather ----
    {
        const float* bs = (const float*)(sm + OFF_S);
        float cQK  = __ldg(g_CONST + 0);
        float ckwp = __ldg(g_CONST + 8);
        for (int p = tid; p < NPOL; p += 384) {
            int r = g_MAP[p];
            float v;
            if (r < 13122) {
                int rr = (r < 6561) ? r : r - 6561;
                int q = rr / 81, k = rr - q * 81;
                v = bs[q * 96 + k] + bs[90 * 96 + q] + bs[89 * 96 + k] + cQK;
                if (r >= 6561) v += bs[88 * 96 + k] + ckwp;       // promo: + kwp[k]
            } else {
                int r3 = r - 13122;
                int n = r3 / 81, k = r3 - n * 81;
                v = bs[(81 + n) * 96 + k] + __ldg(g_CONST + 1 + n);
            }
            out[(size_t)b * NPOL + p] = v;
        }
    }
}

// ---------------- launch ----------------
extern "C" void kernel_launch(void* const* d_in, const int* in_sizes, int n_in,
                              void* d_out, int out_size) {
    const float* x   = (const float*)d_in[0];
    const float* We  = (const float*)d_in[1];
    const float* be  = (const float*)d_in[2];
    const float* Wq  = (const float*)d_in[3];
    const float* bq  = (const float*)d_in[4];
    const float* Wk  = (const float*)d_in[5];
    const float* bk  = (const float*)d_in[6];
    const float* Wp  = (const float*)d_in[7];
    const float* bp  = (const float*)d_in[8];
    const float* dq  = (const float*)d_in[9];
    const void*  raw = d_in[10];
    const void*  pol = d_in[11];
    float* out = (float*)d_out;

    cudaFuncSetAttribute(k_fused, cudaFuncAttributeMaxDynamicSharedMemorySize, SMEM_TOT);

    prep_we    <<<256, 256>>>(We);
    prep_w2    <<<256, 256>>>(Wq, Wk);
    prep_small <<<256, 32>>>(Wq, Wk, Wp, bq, bk, dq);
    prep_consts<<<1, 256>>>(bq, bk, Wp, bp, dq);
    prep_map   <<<16, 256>>>(raw, pol);
    k_fused    <<<NB, 384, SMEM_TOT>>>(x, be, out);
}